// round 5
// baseline (speedup 1.0000x reference)
#include <cuda_runtime.h>

#define D_DIM 64
#define H_DIM 256
#define W_DIM 256
#define PLANE (H_DIM * W_DIM)
#define D_CHUNK 8   // outputs per block along D (4 shared pairs)

#define WT 64                 // W tile per block
#define HT 4                  // H tile per block
#define SW (WT + 2)           // 66
#define SH (HT + 2)           // 6
#define SN (SW * SH)          // 396 staged values per plane

// compare-exchange: a=min, b=max
__device__ __forceinline__ void s2(float& a, float& b) {
    float t = fminf(a, b);
    b = fmaxf(a, b);
    a = t;
}

// Optimal 9-input sorting network: 25 comparators, depth 7.
__device__ __forceinline__ void sort9(float* v) {
    s2(v[0],v[3]); s2(v[1],v[7]); s2(v[2],v[5]); s2(v[4],v[8]);
    s2(v[0],v[7]); s2(v[2],v[4]); s2(v[3],v[8]); s2(v[5],v[6]);
    s2(v[0],v[2]); s2(v[1],v[3]); s2(v[4],v[5]); s2(v[7],v[8]);
    s2(v[1],v[4]); s2(v[3],v[6]); s2(v[5],v[7]);
    s2(v[0],v[1]); s2(v[2],v[4]); s2(v[3],v[5]); s2(v[6],v[8]);
    s2(v[2],v[3]); s2(v[4],v[5]); s2(v[6],v[7]);
    s2(v[1],v[2]); s2(v[3],v[4]); s2(v[5],v[6]);
}

// ---- Batcher odd-even merges of two sorted arrays ----
__device__ __forceinline__ void merge11(const float* a, const float* b, float* c) {
    c[0] = a[0]; c[1] = b[0]; s2(c[0], c[1]);
}
__device__ __forceinline__ void merge22(const float* a, const float* b, float* c) {
    float ae[1] = {a[0]}, be[1] = {b[0]}, ao[1] = {a[1]}, bo[1] = {b[1]};
    float e[2], o[2];
    merge11(ae, be, e); merge11(ao, bo, o);
    c[0] = e[0];
    c[1] = o[0]; c[2] = e[1]; s2(c[1], c[2]);
    c[3] = o[1];
}
__device__ __forceinline__ void merge33(const float* a, const float* b, float* c) {
    float ae[2] = {a[0], a[2]}, be[2] = {b[0], b[2]};
    float ao[1] = {a[1]},       bo[1] = {b[1]};
    float e[4], o[2];
    merge22(ae, be, e); merge11(ao, bo, o);
    c[0] = e[0];
    c[1] = o[0]; c[2] = e[1]; s2(c[1], c[2]);
    c[3] = o[1]; c[4] = e[2]; s2(c[3], c[4]);
    c[5] = e[3];
}
__device__ __forceinline__ void merge44(const float* a, const float* b, float* c) {
    float ae[2] = {a[0], a[2]}, be[2] = {b[0], b[2]};
    float ao[2] = {a[1], a[3]}, bo[2] = {b[1], b[3]};
    float e[4], o[4];
    merge22(ae, be, e); merge22(ao, bo, o);
    c[0] = e[0];
    c[1] = o[0]; c[2] = e[1]; s2(c[1], c[2]);
    c[3] = o[1]; c[4] = e[2]; s2(c[3], c[4]);
    c[5] = o[2]; c[6] = e[3]; s2(c[5], c[6]);
    c[7] = o[3];
}
__device__ __forceinline__ void merge55(const float* a, const float* b, float* c) {
    float ae[3] = {a[0], a[2], a[4]}, be[3] = {b[0], b[2], b[4]};
    float ao[2] = {a[1], a[3]},       bo[2] = {b[1], b[3]};
    float e[6], o[4];
    merge33(ae, be, e); merge22(ao, bo, o);
    c[0] = e[0];
#pragma unroll
    for (int i = 1; i <= 4; ++i) { c[2*i-1] = o[i-1]; c[2*i] = e[i]; s2(c[2*i-1], c[2*i]); }
    c[9] = e[5];
}
// Full merge of two sorted 9s into sorted 18 (ends dead-coded by compiler).
__device__ __forceinline__ void merge99(const float* a, const float* b, float* c) {
    float ae[5] = {a[0], a[2], a[4], a[6], a[8]};
    float be[5] = {b[0], b[2], b[4], b[6], b[8]};
    float ao[4] = {a[1], a[3], a[5], a[7]};
    float bo[4] = {b[1], b[3], b[5], b[7]};
    float e[10], o[8];
    merge55(ae, be, e); merge44(ao, bo, o);
    c[0] = e[0];
#pragma unroll
    for (int i = 1; i <= 8; ++i) { c[2*i-1] = o[i-1]; c[2*i] = e[i]; s2(c[2*i-1], c[2*i]); }
    c[17] = e[9];
}

// 10th smallest of sorted X[0..8] ∪ sorted T[0..9]  (== median of the 27-window).
// Closed form: max( T[0], max_i min(X[i], T[9-i]) ).
__device__ __forceinline__ float select10(const float* X, const float* T) {
    float c0 = T[0];
    float c1 = fminf(X[0], T[9]);
    float c2 = fminf(X[1], T[8]);
    float c3 = fminf(X[2], T[7]);
    float c4 = fminf(X[3], T[6]);
    float c5 = fminf(X[4], T[5]);
    float c6 = fminf(X[5], T[4]);
    float c7 = fminf(X[6], T[3]);
    float c8 = fminf(X[7], T[2]);
    float c9 = fminf(X[8], T[1]);
    float m01 = fmaxf(c0, c1), m23 = fmaxf(c2, c3);
    float m45 = fmaxf(c4, c5), m67 = fmaxf(c6, c7);
    float m89 = fmaxf(c8, c9);
    return fmaxf(fmaxf(fmaxf(m01, m23), fmaxf(m45, m67)), m89);
}

__global__ void __launch_bounds__(256)
median3d_kernel(const float* __restrict__ x, float* __restrict__ y) {
    __shared__ float sbuf[2][SN];

    const int tid = threadIdx.x;            // 0..255
    const int tx = tid & (WT - 1);          // 0..63
    const int ty = tid >> 6;                // 0..3
    const int w0 = blockIdx.x * WT;
    const int h0 = blockIdx.y * HT;
    const int d0 = blockIdx.z * D_CHUNK;

    // ---- d-invariant staging slots (each thread stages <=2 halo-tile cells) ----
    // slot 0: idx = tid; slot 1: idx = tid + 256 (valid if < SN)
    int off0 = 0, off1 = 0;
    bool v0, v1;
    {
        int r = tid / SW, c = tid - r * SW;
        int gh = h0 - 1 + r, gw = w0 - 1 + c;
        v0 = (gh >= 0) && (gh < H_DIM) && (gw >= 0) && (gw < W_DIM);
        if (v0) off0 = gh * W_DIM + gw;
    }
    const int idx1 = tid + 256;
    const bool has1 = (idx1 < SN);
    {
        int r = idx1 / SW, c = idx1 - r * SW;
        int gh = h0 - 1 + r, gw = w0 - 1 + c;
        v1 = has1 && (gh >= 0) && (gh < H_DIM) && (gw >= 0) && (gw < W_DIM);
        if (v1) off1 = gh * W_DIM + gw;
    }
    // smem read base for this thread's 3x3 neighborhood
    const int rb = ty * SW + tx;            // row ty (= global h0+ty-1), col tx (= w0+tx-1)

    const float* xb = x;
    float* o0 = y + (size_t)(h0 + ty) * W_DIM + (w0 + tx);

    float Pm[9], P0[9], P1[9], P2[9];       // sorted planes d-1, d, d+1, d+2
    float c[18];

    // stage plane k into sbuf[k&1], sync, read 9, sort. k in [0,64) guaranteed.
#define SORTLOAD(P, k)                                                        \
    do {                                                                      \
        float* sb = sbuf[(k) & 1];                                            \
        const float* p = xb + (size_t)(k) * PLANE;                            \
        sb[tid] = v0 ? __ldg(p + off0) : 0.0f;                                \
        if (has1) sb[idx1] = v1 ? __ldg(p + off1) : 0.0f;                     \
        __syncthreads();                                                      \
        P[0] = sb[rb];          P[1] = sb[rb + 1];          P[2] = sb[rb + 2];\
        P[3] = sb[rb + SW];     P[4] = sb[rb + SW + 1];     P[5] = sb[rb + SW + 2];\
        P[6] = sb[rb + 2*SW];   P[7] = sb[rb + 2*SW + 1];   P[8] = sb[rb + 2*SW + 2];\
        sort9(P);                                                             \
    } while (0)

    // plane d0-1 (zero pad if d0 == 0)
    if (d0 == 0) {
#pragma unroll
        for (int i = 0; i < 9; ++i) Pm[i] = 0.0f;
    } else {
        SORTLOAD(Pm, d0 - 1);
    }
    // plane d0
    SORTLOAD(P0, d0);

#pragma unroll
    for (int pp = 0; pp < D_CHUNK / 2; ++pp) {
        const int d = d0 + 2 * pp;          // pair (d, d+1); d <= 62

        SORTLOAD(P1, d + 1);                // always exists

        if (d + 2 < D_DIM) {
            SORTLOAD(P2, d + 2);
        } else {
#pragma unroll
            for (int i = 0; i < 9; ++i) P2[i] = 0.0f;   // plane 64 = zero pad
        }

        // shared sorted merge of planes (d, d+1); middle 10 = c[4..13]
        merge99(P0, P1, c);

        // two independent rank selections (high ILP)
        o0[(size_t)d * PLANE]       = select10(Pm, c + 4);
        o0[(size_t)(d + 1) * PLANE] = select10(P2, c + 4);

        // slide by 2: Pm <- P1, P0 <- P2 (register-renamed under full unroll)
#pragma unroll
        for (int i = 0; i < 9; ++i) { Pm[i] = P1[i]; P0[i] = P2[i]; }
    }
#undef SORTLOAD
}

extern "C" void kernel_launch(void* const* d_in, const int* in_sizes, int n_in,
                              void* d_out, int out_size) {
    const float* x = (const float*)d_in[0];
    float* y = (float*)d_out;
    dim3 block(256, 1, 1);
    dim3 grid(W_DIM / WT, H_DIM / HT, D_DIM / D_CHUNK);  // (4, 64, 8) = 2048 CTAs
    median3d_kernel<<<grid, block>>>(x, y);
}